// round 5
// baseline (speedup 1.0000x reference)
#include <cuda_runtime.h>
#include <math.h>
#include <stdint.h>

#define B_SZ   4
#define L_SEQ  2048
#define E_DIM  2048
#define NH     16
#define HD     128
#define M_TOTAL (B_SZ * L_SEQ)   /* 8192 */
#define K_DIM   E_DIM            /* 2048 */
#define N_TOTAL (3 * E_DIM)      /* 6144 */

// Scratch: QKV output + tf32-pre-rounded copies of x and W.
__device__ float g_y [(size_t)M_TOTAL * (size_t)N_TOTAL];   // ~201 MB
__device__ float g_xr[(size_t)M_TOTAL * (size_t)K_DIM];     // ~67 MB
__device__ float g_wr[(size_t)N_TOTAL * (size_t)K_DIM];     // ~50 MB

// ---------------------------------------------------------------------------
// PTX helpers
// ---------------------------------------------------------------------------
__device__ __forceinline__ uint32_t f2tf32(float f) {
    uint32_t r;
    asm("cvt.rna.tf32.f32 %0, %1;" : "=r"(r) : "f"(f));
    return r;
}
__device__ __forceinline__ uint32_t fu(float f) { return __float_as_uint(f); }

__device__ __forceinline__ uint32_t smem_u32(const void* p) {
    uint32_t a;
    asm("{ .reg .u64 t; cvta.to.shared.u64 t, %1; cvt.u32.u64 %0, t; }"
        : "=r"(a) : "l"(p));
    return a;
}

#define MMA_TF32(c, a0, a1, a2, a3, b0, b1)                                   \
    asm volatile(                                                             \
        "mma.sync.aligned.m16n8k8.row.col.f32.tf32.tf32.f32 "                 \
        "{%0,%1,%2,%3}, {%4,%5,%6,%7}, {%8,%9}, {%0,%1,%2,%3};"               \
        : "+f"((c)[0]), "+f"((c)[1]), "+f"((c)[2]), "+f"((c)[3])              \
        : "r"(a0), "r"(a1), "r"(a2), "r"(a3), "r"(b0), "r"(b1))

#define LDSM_X4(r0, r1, r2, r3, addr)                                         \
    asm volatile("ldmatrix.sync.aligned.m8n8.x4.shared.b16 "                  \
                 "{%0,%1,%2,%3}, [%4];"                                       \
                 : "=r"(r0), "=r"(r1), "=r"(r2), "=r"(r3) : "r"(addr))

#define CP_ASYNC16(dst, src)                                                  \
    asm volatile("cp.async.cg.shared.global [%0], [%1], 16;"                  \
                 :: "r"(dst), "l"(src))
#define CP_COMMIT() asm volatile("cp.async.commit_group;" ::: "memory")
#define CP_WAIT(n)  asm volatile("cp.async.wait_group %0;" :: "n"(n) : "memory")

// ===========================================================================
// Kernel 0: elementwise tf32 pre-round (x -> g_xr, W -> g_wr)
// ===========================================================================
__global__ __launch_bounds__(256) void preround_kernel(
    const float* __restrict__ src, float* __restrict__ dst, int n4)
{
    int i = blockIdx.x * blockDim.x + threadIdx.x;
    if (i >= n4) return;
    float4 v = ((const float4*)src)[i];
    float4 o;
    o.x = __uint_as_float(f2tf32(v.x));
    o.y = __uint_as_float(f2tf32(v.y));
    o.z = __uint_as_float(f2tf32(v.z));
    o.w = __uint_as_float(f2tf32(v.w));
    ((float4*)dst)[i] = o;
}

// ===========================================================================
// Kernel 1: QKV GEMM with FUSED bias + L2-norm + tf32-round epilogue.
// Each 128-wide N tile is exactly one q/k/v block of one head
// (comp = blockIdx.x % 3): q,k get row-normalized; all get tf32-rounded.
// ===========================================================================
#define GSTR 36
#define G_STAGE_F (2 * 128 * GSTR)
#define G_SMEM_BYTES (3 * G_STAGE_F * 4)

__global__ __launch_bounds__(256, 2) void qkv_gemm_v3(
    const float* __restrict__ bias)
{
    extern __shared__ __align__(16) float gs[];
    const uint32_t sbase = smem_u32(gs);

    const int tid  = threadIdx.x;
    const int lane = tid & 31;
    const int wid  = tid >> 5;
    const int gid  = lane >> 2;
    const int tig  = lane & 3;
    const int wm   = wid & 3;
    const int wn   = wid >> 2;
    const int m0   = blockIdx.y * 128;
    const int n0   = blockIdx.x * 128;

    const uint32_t a_lm = (uint32_t)(((lane & 15) * GSTR + (lane >> 4) * 4) * 4);
    const uint32_t b_lm = (uint32_t)((((lane & 7) + (lane >> 4) * 8) * GSTR
                                      + ((lane >> 3) & 1) * 4) * 4);
    const int cp_r = tid >> 3;
    const int cp_c = tid & 7;

    float C[2][8][4];
#pragma unroll
    for (int t = 0; t < 2; t++)
#pragma unroll
        for (int u = 0; u < 8; u++)
#pragma unroll
            for (int j = 0; j < 4; j++) C[t][u][j] = 0.f;

    const int NIT = K_DIM / 32;

    auto stage_load = [&](int it, int st) {
        const int k0 = it * 32;
        const uint32_t sb = sbase + (uint32_t)(st * G_STAGE_F * 4);
#pragma unroll
        for (int i = 0; i < 4; i++) {
            int r = i * 32 + cp_r;
            uint32_t dst = sb + (uint32_t)((r * GSTR + cp_c * 4) * 4);
            const float* src = g_xr + (size_t)(m0 + r) * K_DIM + k0 + cp_c * 4;
            CP_ASYNC16(dst, src);
        }
#pragma unroll
        for (int i = 0; i < 4; i++) {
            int r = i * 32 + cp_r;
            uint32_t dst = sb + (uint32_t)((4608 + r * GSTR + cp_c * 4) * 4);
            const float* src = g_wr + (size_t)(n0 + r) * K_DIM + k0 + cp_c * 4;
            CP_ASYNC16(dst, src);
        }
    };

    stage_load(0, 0); CP_COMMIT();
    stage_load(1, 1); CP_COMMIT();

    for (int it = 0; it < NIT; ++it) {
        CP_WAIT(1);
        __syncthreads();
        if (it + 2 < NIT) stage_load(it + 2, (it + 2) % 3);
        CP_COMMIT();

        const uint32_t sb = sbase + (uint32_t)(((it % 3) * G_STAGE_F) * 4);
        const uint32_t aB = sb + (uint32_t)(wm * 32 * GSTR * 4) + a_lm;
        const uint32_t bB = sb + (uint32_t)((4608 + wn * 64 * GSTR) * 4) + b_lm;

#pragma unroll
        for (int s = 0; s < 4; s++) {
            uint32_t a0[4], a1[4];
            LDSM_X4(a0[0], a0[1], a0[2], a0[3], aB + s * 32);
            LDSM_X4(a1[0], a1[1], a1[2], a1[3], aB + 16 * GSTR * 4 + s * 32);
#pragma unroll
            for (int up = 0; up < 4; up++) {
                uint32_t b[4];
                LDSM_X4(b[0], b[1], b[2], b[3],
                        bB + up * 16 * GSTR * 4 + s * 32);
                MMA_TF32(C[0][up * 2],     a0[0], a0[1], a0[2], a0[3], b[0], b[1]);
                MMA_TF32(C[0][up * 2 + 1], a0[0], a0[1], a0[2], a0[3], b[2], b[3]);
                MMA_TF32(C[1][up * 2],     a1[0], a1[1], a1[2], a1[3], b[0], b[1]);
                MMA_TF32(C[1][up * 2 + 1], a1[0], a1[1], a1[2], a1[3], b[2], b[3]);
            }
        }
    }

    // ---------------- fused epilogue ----------------
    CP_WAIT(0);
    __syncthreads();                 // mainloop smem now reusable
    float* red = gs;                 // [128][2] row partial norms
    const int comp = blockIdx.x % 3; // 0=q 1=k 2=v

    // bias add (fp32, pre-normalization, matches reference order)
#pragma unroll
    for (int t = 0; t < 2; t++)
#pragma unroll
        for (int u = 0; u < 8; u++) {
            int col = n0 + wn * 64 + u * 8 + tig * 2;
            float2 bv = *(const float2*)&bias[col];
            C[t][u][0] += bv.x; C[t][u][1] += bv.y;
            C[t][u][2] += bv.x; C[t][u][3] += bv.y;
        }

    float sc[2][2] = {{1.f, 1.f}, {1.f, 1.f}};
    if (comp < 2) {
#pragma unroll
        for (int t = 0; t < 2; t++)
#pragma unroll
            for (int hh = 0; hh < 2; hh++) {
                float p = 0.f;
#pragma unroll
                for (int u = 0; u < 8; u++)
                    p += C[t][u][2 * hh] * C[t][u][2 * hh]
                       + C[t][u][2 * hh + 1] * C[t][u][2 * hh + 1];
                p += __shfl_xor_sync(0xffffffffu, p, 1);
                p += __shfl_xor_sync(0xffffffffu, p, 2);
                if (tig == 0)
                    red[(wm * 32 + t * 16 + hh * 8 + gid) * 2 + wn] = p;
            }
        __syncthreads();
#pragma unroll
        for (int t = 0; t < 2; t++)
#pragma unroll
            for (int hh = 0; hh < 2; hh++) {
                int r = wm * 32 + t * 16 + hh * 8 + gid;
                float s = red[r * 2] + red[r * 2 + 1];
                sc[t][hh] = 1.0f / fmaxf(sqrtf(s), 1e-12f);
            }
    }

#pragma unroll
    for (int t = 0; t < 2; t++) {
        int r0 = m0 + wm * 32 + t * 16 + gid;
#pragma unroll
        for (int u = 0; u < 8; u++) {
            int col = n0 + wn * 64 + u * 8 + tig * 2;
            uint2 o0 = make_uint2(f2tf32(C[t][u][0] * sc[t][0]),
                                  f2tf32(C[t][u][1] * sc[t][0]));
            uint2 o1 = make_uint2(f2tf32(C[t][u][2] * sc[t][1]),
                                  f2tf32(C[t][u][3] * sc[t][1]));
            *(uint2*)&g_y[(size_t)r0 * N_TOTAL + col]       = o0;
            *(uint2*)&g_y[(size_t)(r0 + 8) * N_TOTAL + col] = o1;
        }
    }
}

// ===========================================================================
// Kernel 2: attention. BM=128 (8 warps x 16 rows), BN=64.
// Q frags persistent in regs; K/V double-buffered via cp.async; V transposed
// in smem once per tile so PV B-frags come from ldmatrix (no scalar LDS).
// ===========================================================================
#define KSTR  132
#define VRSTR 132
#define TSTR  68
#define PSTR  68
#define K_OFF(buf)  ((buf) * (64 * KSTR))
#define VR_OFF(buf) (2 * 64 * KSTR + (buf) * (64 * VRSTR))
#define VT_OFF      (2 * 64 * KSTR + 2 * 64 * VRSTR)
#define P_OFF       (VT_OFF + 128 * TSTR)
#define ATT_SMEM_FLOATS (P_OFF + 128 * PSTR)   /* 51200 floats = 200 KB */

__device__ __forceinline__ float exp_poly(float x) {
    float p = fmaf(x, 2.48015873e-5f, 1.98412698e-4f);
    p = fmaf(x, p, 1.38888889e-3f);
    p = fmaf(x, p, 8.33333333e-3f);
    p = fmaf(x, p, 4.16666667e-2f);
    p = fmaf(x, p, 1.66666667e-1f);
    p = fmaf(x, p, 0.5f);
    p = fmaf(x, p, 1.0f);
    p = fmaf(x, p, 1.0f);
    return p;
}

__global__ __launch_bounds__(256, 1) void attn_v3(float* __restrict__ out)
{
    extern __shared__ __align__(16) float sm[];
    const uint32_t sbase = smem_u32(sm);

    const int tid  = threadIdx.x;
    const int lane = tid & 31;
    const int wid  = tid >> 5;
    const int gid  = lane >> 2;
    const int tig  = lane & 3;
    const int rbase = wid * 16;
    const int m0   = blockIdx.x * 128;
    const int bh   = blockIdx.y;
    const int bb   = bh >> 4;
    const int h    = bh & 15;
    const size_t head_base =
        (size_t)bb * L_SEQ * N_TOTAL + (size_t)h * (3 * HD);

    // persistent Q fragments
    uint32_t Qf[16][4];
    {
        const size_t rq = head_base + (size_t)(m0 + rbase + gid) * N_TOTAL;
#pragma unroll
        for (int s = 0; s < 16; s++) {
            int col = s * 8 + tig;
            Qf[s][0] = fu(g_y[rq + col]);
            Qf[s][1] = fu(g_y[rq + 8 * N_TOTAL + col]);
            Qf[s][2] = fu(g_y[rq + col + 4]);
            Qf[s][3] = fu(g_y[rq + 8 * N_TOTAL + col + 4]);
        }
    }

    // ldmatrix lane offsets (bytes)
    const uint32_t row8 = (uint32_t)((lane & 7) + (lane >> 4) * 8);
    const uint32_t chk  = (uint32_t)(((lane >> 3) & 1) * 4);
    const uint32_t k_lm  = (uint32_t)((row8 * KSTR + chk) * 4);
    const uint32_t vt_lm = sbase + (uint32_t)((VT_OFF + row8 * TSTR + chk) * 4);
    const uint32_t p_lm  = sbase +
        (uint32_t)((P_OFF + (rbase + (lane & 15)) * PSTR + (lane >> 4) * 4) * 4);

    const int cp_c = tid & 31;

    auto stage_load = [&](int tt, int buf) {
        const int n0t = tt * 64;
#pragma unroll
        for (int i = 0; i < 8; i++) {        // K
            int r = i * 8 + wid;
            uint32_t dst = sbase + (uint32_t)((K_OFF(buf) + r * KSTR + cp_c * 4) * 4);
            const float* src = g_y + head_base + (size_t)(n0t + r) * N_TOTAL
                               + HD + cp_c * 4;
            CP_ASYNC16(dst, src);
        }
#pragma unroll
        for (int i = 0; i < 8; i++) {        // V (raw)
            int r = i * 8 + wid;
            uint32_t dst = sbase + (uint32_t)((VR_OFF(buf) + r * VRSTR + cp_c * 4) * 4);
            const float* src = g_y + head_base + (size_t)(n0t + r) * N_TOTAL
                               + 2 * HD + cp_c * 4;
            CP_ASYNC16(dst, src);
        }
    };

    float O[16][4];
#pragma unroll
    for (int u = 0; u < 16; u++)
#pragma unroll
        for (int j = 0; j < 4; j++) O[u][j] = 0.f;
    float l0 = 0.f, l1 = 0.f;

    float* Ps = sm + P_OFF;
    float* Vt = sm + VT_OFF;

    stage_load(0, 0); CP_COMMIT();

    for (int tt = 0; tt < L_SEQ / 64; ++tt) {
        CP_WAIT(0);
        __syncthreads();
        if (tt + 1 < L_SEQ / 64) stage_load(tt + 1, (tt + 1) & 1);
        CP_COMMIT();

        const int buf = tt & 1;
        const uint32_t kB = sbase + (uint32_t)(K_OFF(buf) * 4) + k_lm;

        // ---- transpose V: [64 kv][128 d] -> Vt [128 d][64 kv] ----
        // mapping keeps kv varying across lanes: conflict-free LDS/STS.
        {
            const float* Vr = sm + VR_OFF(buf);
#pragma unroll
            for (int i = 0; i < 8; i++) {
                int idx = i * 256 + tid;        // float4 id 0..2047
                int kv  = idx & 63;
                int dc  = (idx >> 6) * 4;       // 0..124
                float4 v = *(const float4*)&Vr[kv * VRSTR + dc];
                Vt[(dc + 0) * TSTR + kv] = v.x;
                Vt[(dc + 1) * TSTR + kv] = v.y;
                Vt[(dc + 2) * TSTR + kv] = v.z;
                Vt[(dc + 3) * TSTR + kv] = v.w;
            }
        }

        // ---- S = Q . K^T ----
        float S[8][4];
#pragma unroll
        for (int u = 0; u < 8; u++)
#pragma unroll
            for (int j = 0; j < 4; j++) S[u][j] = 0.f;

#pragma unroll
        for (int s = 0; s < 16; s++) {
#pragma unroll
            for (int up = 0; up < 4; up++) {
                uint32_t b[4];
                LDSM_X4(b[0], b[1], b[2], b[3],
                        kB + up * 16 * KSTR * 4 + s * 32);
                MMA_TF32(S[up * 2],     Qf[s][0], Qf[s][1], Qf[s][2], Qf[s][3],
                         b[0], b[1]);
                MMA_TF32(S[up * 2 + 1], Qf[s][0], Qf[s][1], Qf[s][2], Qf[s][3],
                         b[2], b[3]);
            }
        }

        // ---- exp, accumulate l, stage P (tf32) ----
#pragma unroll
        for (int u = 0; u < 8; u++) {
            float p0 = exp_poly(S[u][0]);
            float p1 = exp_poly(S[u][1]);
            float p2 = exp_poly(S[u][2]);
            float p3 = exp_poly(S[u][3]);
            l0 += p0 + p1;
            l1 += p2 + p3;
            *(uint2*)&Ps[(rbase + gid) * PSTR + u * 8 + tig * 2] =
                make_uint2(f2tf32(p0), f2tf32(p1));
            *(uint2*)&Ps[(rbase + 8 + gid) * PSTR + u * 8 + tig * 2] =
                make_uint2(f2tf32(p2), f2tf32(p3));
        }
        __syncthreads();   // Vt complete (all warps) + own P staged

        // ---- O += P . V  (both operands via ldmatrix) ----
#pragma unroll
        for (int s = 0; s < 8; s++) {
            uint32_t a[4];
            LDSM_X4(a[0], a[1], a[2], a[3], p_lm + s * 32);
#pragma unroll
            for (int db = 0; db < 8; db++) {
                uint32_t b[4];
                LDSM_X4(b[0], b[1], b[2], b[3],
                        vt_lm + db * (16 * TSTR * 4) + s * 32);
                MMA_TF32(O[db * 2],     a[0], a[1], a[2], a[3], b[0], b[1]);
                MMA_TF32(O[db * 2 + 1], a[0], a[1], a[2], a[3], b[2], b[3]);
            }
        }
    }

    // ---- epilogue ----
    l0 += __shfl_xor_sync(0xffffffffu, l0, 1);
    l0 += __shfl_xor_sync(0xffffffffu, l0, 2);
    l1 += __shfl_xor_sync(0xffffffffu, l1, 1);
    l1 += __shfl_xor_sync(0xffffffffu, l1, 2);
    const float inv0 = 1.0f / l0;
    const float inv1 = 1.0f / l1;

    const int r0 = m0 + rbase + gid;
    float* o0 = &out[((size_t)(bb * L_SEQ + r0)) * E_DIM + h * HD];
    float* o1 = &out[((size_t)(bb * L_SEQ + r0 + 8)) * E_DIM + h * HD];
#pragma unroll
    for (int ud = 0; ud < 16; ud++) {
        int col = ud * 8 + tig * 2;
        *(float2*)&o0[col] = make_float2(O[ud][0] * inv0, O[ud][1] * inv0);
        *(float2*)&o1[col] = make_float2(O[ud][2] * inv1, O[ud][3] * inv1);
    }
}

// ===========================================================================
extern "C" void kernel_launch(void* const* d_in, const int* in_sizes, int n_in,
                              void* d_out, int out_size)
{
    (void)in_sizes; (void)n_in; (void)out_size;
    const float* x = (const float*)d_in[0];
    const float* W = (const float*)d_in[1];
    const float* b = (const float*)d_in[2];
    float* out = (float*)d_out;

    float* xr; cudaGetSymbolAddress((void**)&xr, g_xr);
    float* wr; cudaGetSymbolAddress((void**)&wr, g_wr);

    // 0) tf32 pre-round of x and W (RNA)
    int nx4 = (M_TOTAL * K_DIM) / 4;
    int nw4 = (N_TOTAL * K_DIM) / 4;
    preround_kernel<<<(nx4 + 255) / 256, 256>>>(x, xr, nx4);
    preround_kernel<<<(nw4 + 255) / 256, 256>>>(W, wr, nw4);

    // 1) QKV projection with fused bias + L2-norm + tf32-round epilogue
    cudaFuncSetAttribute(qkv_gemm_v3,
                         cudaFuncAttributeMaxDynamicSharedMemorySize, G_SMEM_BYTES);
    qkv_gemm_v3<<<dim3(N_TOTAL / 128, M_TOTAL / 128), 256, G_SMEM_BYTES>>>(b);

    // 2) Attention
    size_t asmem = (size_t)ATT_SMEM_FLOATS * sizeof(float);   // 204800 B
    cudaFuncSetAttribute(attn_v3,
                         cudaFuncAttributeMaxDynamicSharedMemorySize, (int)asmem);
    attn_v3<<<dim3(L_SEQ / 128, B_SZ * NH), 256, asmem>>>(out);
}

// round 6
// speedup vs baseline: 1.9231x; 1.9231x over previous
#include <cuda_runtime.h>
#include <cuda_fp16.h>
#include <math.h>
#include <stdint.h>

#define B_SZ   4
#define L_SEQ  2048
#define E_DIM  2048
#define NH     16
#define HD     128
#define M_TOTAL (B_SZ * L_SEQ)   /* 8192 */
#define K_DIM   E_DIM            /* 2048 */
#define N_TOTAL (3 * E_DIM)      /* 6144 */

// Scratch: fp16 copies of x, W; fp16 QKV output.
__device__ __half g_xh[(size_t)M_TOTAL * (size_t)K_DIM];    // ~33 MB
__device__ __half g_wh[(size_t)N_TOTAL * (size_t)K_DIM];    // ~25 MB
__device__ __half g_yh[(size_t)M_TOTAL * (size_t)N_TOTAL];  // ~100 MB

// ---------------------------------------------------------------------------
// PTX helpers
// ---------------------------------------------------------------------------
__device__ __forceinline__ uint32_t smem_u32(const void* p) {
    uint32_t a;
    asm("{ .reg .u64 t; cvta.to.shared.u64 t, %1; cvt.u32.u64 %0, t; }"
        : "=r"(a) : "l"(p));
    return a;
}

#define MMA_F16(c, a0, a1, a2, a3, b0, b1)                                    \
    asm volatile(                                                             \
        "mma.sync.aligned.m16n8k16.row.col.f32.f16.f16.f32 "                  \
        "{%0,%1,%2,%3}, {%4,%5,%6,%7}, {%8,%9}, {%0,%1,%2,%3};"               \
        : "+f"((c)[0]), "+f"((c)[1]), "+f"((c)[2]), "+f"((c)[3])              \
        : "r"(a0), "r"(a1), "r"(a2), "r"(a3), "r"(b0), "r"(b1))

#define LDSM_X4(r0, r1, r2, r3, addr)                                         \
    asm volatile("ldmatrix.sync.aligned.m8n8.x4.shared.b16 "                  \
                 "{%0,%1,%2,%3}, [%4];"                                       \
                 : "=r"(r0), "=r"(r1), "=r"(r2), "=r"(r3) : "r"(addr))

#define LDSM_X4_T(r0, r1, r2, r3, addr)                                       \
    asm volatile("ldmatrix.sync.aligned.m8n8.x4.trans.shared.b16 "            \
                 "{%0,%1,%2,%3}, [%4];"                                       \
                 : "=r"(r0), "=r"(r1), "=r"(r2), "=r"(r3) : "r"(addr))

#define CP_ASYNC16(dst, src)                                                  \
    asm volatile("cp.async.cg.shared.global [%0], [%1], 16;"                  \
                 :: "r"(dst), "l"(src))
#define CP_COMMIT() asm volatile("cp.async.commit_group;" ::: "memory")
#define CP_WAIT(n)  asm volatile("cp.async.wait_group %0;" :: "n"(n) : "memory")

// ===========================================================================
// Kernel 0: fp32 -> fp16 (RN) conversion of x and W
// ===========================================================================
__global__ __launch_bounds__(256) void to_half_kernel(
    const float* __restrict__ src, __half* __restrict__ dst, int n4)
{
    int i = blockIdx.x * blockDim.x + threadIdx.x;
    if (i >= n4) return;
    float4 v = ((const float4*)src)[i];
    __half2 h0 = __floats2half2_rn(v.x, v.y);
    __half2 h1 = __floats2half2_rn(v.z, v.w);
    ((uint2*)dst)[i] = make_uint2(*(uint32_t*)&h0, *(uint32_t*)&h1);
}

// ===========================================================================
// Kernel 1: QKV GEMM (fp16 MMA, fp32 accum) with fused bias+L2norm epilogue.
// 128x128 tile, BK=64 halves, 3-stage cp.async, 8 warps 4(M)x2(N).
// N tile == one q/k/v block of one head (comp = blockIdx.x % 3).
// ===========================================================================
#define GSTR 72                       /* 64 + 8 halves pad */
#define G_STAGE_H (2 * 128 * GSTR)    /* A then B, halves */
#define G_SMEM_BYTES (3 * G_STAGE_H * 2)   /* 110592 B */

__global__ __launch_bounds__(256, 2) void qkv_gemm_h(
    const float* __restrict__ bias)
{
    extern __shared__ __align__(16) __half gsh[];
    const uint32_t sbase = smem_u32(gsh);
    float* red = (float*)gsh;          // epilogue reuse

    const int tid  = threadIdx.x;
    const int lane = tid & 31;
    const int wid  = tid >> 5;
    const int gid  = lane >> 2;
    const int tig  = lane & 3;
    const int wm   = wid & 3;
    const int wn   = wid >> 2;
    const int m0   = blockIdx.y * 128;
    const int n0   = blockIdx.x * 128;

    // ldmatrix lane byte offsets
    const uint32_t a_lm = (uint32_t)(((lane & 15) * GSTR + (lane >> 4) * 8) * 2);
    const uint32_t b_lm = (uint32_t)(((((lane & 7) + ((lane >> 4) & 1) * 8) * GSTR)
                                      + ((lane >> 3) & 1) * 8) * 2);
    // cp.async: 64 halves/row = 8 x 16B chunks
    const int cp_r = tid >> 3;        // 0..31
    const int cp_c = tid & 7;

    float C[2][8][4];
#pragma unroll
    for (int t = 0; t < 2; t++)
#pragma unroll
        for (int u = 0; u < 8; u++)
#pragma unroll
            for (int j = 0; j < 4; j++) C[t][u][j] = 0.f;

    const int NIT = K_DIM / 64;   // 32

    auto stage_load = [&](int it, int st) {
        const int k0 = it * 64;
        const uint32_t sb = sbase + (uint32_t)(st * G_STAGE_H * 2);
#pragma unroll
        for (int i = 0; i < 4; i++) {             // A rows
            int r = i * 32 + cp_r;
            uint32_t dst = sb + (uint32_t)((r * GSTR + cp_c * 8) * 2);
            const __half* src = g_xh + (size_t)(m0 + r) * K_DIM + k0 + cp_c * 8;
            CP_ASYNC16(dst, src);
        }
#pragma unroll
        for (int i = 0; i < 4; i++) {             // B rows
            int r = i * 32 + cp_r;
            uint32_t dst = sb + (uint32_t)((128 * GSTR + r * GSTR + cp_c * 8) * 2);
            const __half* src = g_wh + (size_t)(n0 + r) * K_DIM + k0 + cp_c * 8;
            CP_ASYNC16(dst, src);
        }
    };

    stage_load(0, 0); CP_COMMIT();
    stage_load(1, 1); CP_COMMIT();

    for (int it = 0; it < NIT; ++it) {
        CP_WAIT(1);
        __syncthreads();
        if (it + 2 < NIT) stage_load(it + 2, (it + 2) % 3);
        CP_COMMIT();

        const uint32_t sb = sbase + (uint32_t)(((it % 3) * G_STAGE_H) * 2);
        const uint32_t aB = sb + (uint32_t)(wm * 32 * GSTR * 2) + a_lm;
        const uint32_t bB = sb + (uint32_t)((128 + wn * 64) * GSTR * 2) + b_lm;

#pragma unroll
        for (int s = 0; s < 4; s++) {             // 4 x k16
            uint32_t a0[4], a1[4];
            LDSM_X4(a0[0], a0[1], a0[2], a0[3], aB + s * 32);
            LDSM_X4(a1[0], a1[1], a1[2], a1[3], aB + 16 * GSTR * 2 + s * 32);
#pragma unroll
            for (int up = 0; up < 4; up++) {      // 4 x n16
                uint32_t b[4];
                LDSM_X4(b[0], b[1], b[2], b[3],
                        bB + up * 16 * GSTR * 2 + s * 32);
                MMA_F16(C[0][up * 2],     a0[0], a0[1], a0[2], a0[3], b[0], b[1]);
                MMA_F16(C[0][up * 2 + 1], a0[0], a0[1], a0[2], a0[3], b[2], b[3]);
                MMA_F16(C[1][up * 2],     a1[0], a1[1], a1[2], a1[3], b[0], b[1]);
                MMA_F16(C[1][up * 2 + 1], a1[0], a1[1], a1[2], a1[3], b[2], b[3]);
            }
        }
    }

    // ---------------- fused epilogue ----------------
    CP_WAIT(0);
    __syncthreads();
    const int comp = blockIdx.x % 3;  // 0=q 1=k 2=v

#pragma unroll
    for (int t = 0; t < 2; t++)
#pragma unroll
        for (int u = 0; u < 8; u++) {
            int col = n0 + wn * 64 + u * 8 + tig * 2;
            float2 bv = *(const float2*)&bias[col];
            C[t][u][0] += bv.x; C[t][u][1] += bv.y;
            C[t][u][2] += bv.x; C[t][u][3] += bv.y;
        }

    float sc[2][2] = {{1.f, 1.f}, {1.f, 1.f}};
    if (comp < 2) {
#pragma unroll
        for (int t = 0; t < 2; t++)
#pragma unroll
            for (int hh = 0; hh < 2; hh++) {
                float p = 0.f;
#pragma unroll
                for (int u = 0; u < 8; u++)
                    p += C[t][u][2 * hh] * C[t][u][2 * hh]
                       + C[t][u][2 * hh + 1] * C[t][u][2 * hh + 1];
                p += __shfl_xor_sync(0xffffffffu, p, 1);
                p += __shfl_xor_sync(0xffffffffu, p, 2);
                if (tig == 0)
                    red[(wm * 32 + t * 16 + hh * 8 + gid) * 2 + wn] = p;
            }
        __syncthreads();
#pragma unroll
        for (int t = 0; t < 2; t++)
#pragma unroll
            for (int hh = 0; hh < 2; hh++) {
                int r = wm * 32 + t * 16 + hh * 8 + gid;
                float s = red[r * 2] + red[r * 2 + 1];
                sc[t][hh] = 1.0f / fmaxf(sqrtf(s), 1e-12f);
            }
    }

#pragma unroll
    for (int t = 0; t < 2; t++) {
        int r0 = m0 + wm * 32 + t * 16 + gid;
#pragma unroll
        for (int u = 0; u < 8; u++) {
            int col = n0 + wn * 64 + u * 8 + tig * 2;
            __half2 h0 = __floats2half2_rn(C[t][u][0] * sc[t][0],
                                           C[t][u][1] * sc[t][0]);
            __half2 h1 = __floats2half2_rn(C[t][u][2] * sc[t][1],
                                           C[t][u][3] * sc[t][1]);
            *(__half2*)&g_yh[(size_t)r0 * N_TOTAL + col]       = h0;
            *(__half2*)&g_yh[(size_t)(r0 + 8) * N_TOTAL + col] = h1;
        }
    }
}

// ===========================================================================
// Kernel 2: attention, all-fp16 operands, fp32 accum.
// BM=128 (8 warps x 16 rows), BN=64. Q frags persistent (8 k16 steps);
// K B-frags via ldsm.x4; V B-frags via ldsm.x4.trans (no explicit transpose).
// ===========================================================================
#define KSTR 136     /* 128 + 8 halves */
#define VSTR 136
#define PSTR 72      /* 64 + 8 halves */
#define K_OFF_H(buf) ((buf) * (64 * KSTR))
#define V_OFF_H(buf) (2 * 64 * KSTR + (buf) * (64 * VSTR))
#define P_OFF_H      (2 * 64 * KSTR + 2 * 64 * VSTR)
#define ATT_SMEM_BYTES ((P_OFF_H + 128 * PSTR) * 2)   /* 88064 B */

__device__ __forceinline__ float exp_poly(float x) {
    float p = fmaf(x, 2.48015873e-5f, 1.98412698e-4f);
    p = fmaf(x, p, 1.38888889e-3f);
    p = fmaf(x, p, 8.33333333e-3f);
    p = fmaf(x, p, 4.16666667e-2f);
    p = fmaf(x, p, 1.66666667e-1f);
    p = fmaf(x, p, 0.5f);
    p = fmaf(x, p, 1.0f);
    p = fmaf(x, p, 1.0f);
    return p;
}

__global__ __launch_bounds__(256, 1) void attn_h(float* __restrict__ out)
{
    extern __shared__ __align__(16) __half smh[];
    const uint32_t sbase = smem_u32(smh);

    const int tid  = threadIdx.x;
    const int lane = tid & 31;
    const int wid  = tid >> 5;
    const int gid  = lane >> 2;
    const int tig  = lane & 3;
    const int rbase = wid * 16;
    const int m0   = blockIdx.x * 128;
    const int bh   = blockIdx.y;
    const int bb   = bh >> 4;
    const int h    = bh & 15;
    const size_t head_base =
        (size_t)bb * L_SEQ * N_TOTAL + (size_t)h * (3 * HD);

    // ---- persistent Q fragments: 8 k16 steps x 4 regs ----
    uint32_t Qf[8][4];
    {
        const __half* rq = g_yh + head_base + (size_t)(m0 + rbase + gid) * N_TOTAL;
        const __half* rq8 = rq + (size_t)8 * N_TOTAL;
#pragma unroll
        for (int s = 0; s < 8; s++) {
            int c = s * 16 + tig * 2;
            Qf[s][0] = *(const uint32_t*)&rq [c];
            Qf[s][1] = *(const uint32_t*)&rq8[c];
            Qf[s][2] = *(const uint32_t*)&rq [c + 8];
            Qf[s][3] = *(const uint32_t*)&rq8[c + 8];
        }
    }

    // ldmatrix lane byte offsets
    const uint32_t k_lm = (uint32_t)(((((lane & 7) + ((lane >> 4) & 1) * 8) * KSTR)
                                      + ((lane >> 3) & 1) * 8) * 2);
    const uint32_t v_lm = (uint32_t)(((((lane & 7) + ((lane >> 3) & 1) * 8) * VSTR)
                                      + (lane >> 4) * 8) * 2);
    const uint32_t p_lm = sbase +
        (uint32_t)((P_OFF_H + (rbase + (lane & 15)) * PSTR + (lane >> 4) * 8) * 2);

    // cp.async: 128 halves/row = 16 x 16B chunks; 256 thr -> 16 rows/pass
    const int cp_r = tid >> 4;    // 0..15
    const int cp_c = tid & 15;

    auto stage_load = [&](int tt, int buf) {
        const int n0t = tt * 64;
#pragma unroll
        for (int i = 0; i < 4; i++) {        // K: 64 rows
            int r = i * 16 + cp_r;
            uint32_t dst = sbase + (uint32_t)((K_OFF_H(buf) + r * KSTR + cp_c * 8) * 2);
            const __half* src = g_yh + head_base + (size_t)(n0t + r) * N_TOTAL
                                + HD + cp_c * 8;
            CP_ASYNC16(dst, src);
        }
#pragma unroll
        for (int i = 0; i < 4; i++) {        // V: 64 rows
            int r = i * 16 + cp_r;
            uint32_t dst = sbase + (uint32_t)((V_OFF_H(buf) + r * VSTR + cp_c * 8) * 2);
            const __half* src = g_yh + head_base + (size_t)(n0t + r) * N_TOTAL
                                + 2 * HD + cp_c * 8;
            CP_ASYNC16(dst, src);
        }
    };

    float O[16][4];
#pragma unroll
    for (int u = 0; u < 16; u++)
#pragma unroll
        for (int j = 0; j < 4; j++) O[u][j] = 0.f;
    float l0 = 0.f, l1 = 0.f;

    __half* Ps = smh + P_OFF_H;

    stage_load(0, 0); CP_COMMIT();

    for (int tt = 0; tt < L_SEQ / 64; ++tt) {
        CP_WAIT(0);
        __syncthreads();
        if (tt + 1 < L_SEQ / 64) stage_load(tt + 1, (tt + 1) & 1);
        CP_COMMIT();

        const int buf = tt & 1;
        const uint32_t kB = sbase + (uint32_t)(K_OFF_H(buf) * 2) + k_lm;
        const uint32_t vB = sbase + (uint32_t)(V_OFF_H(buf) * 2) + v_lm;

        // ---- S = Q . K^T ----
        float S[8][4];
#pragma unroll
        for (int u = 0; u < 8; u++)
#pragma unroll
            for (int j = 0; j < 4; j++) S[u][j] = 0.f;

#pragma unroll
        for (int s = 0; s < 8; s++) {            // k16 steps over d
#pragma unroll
            for (int up = 0; up < 4; up++) {     // kv 16-blocks
                uint32_t b[4];
                LDSM_X4(b[0], b[1], b[2], b[3],
                        kB + up * 16 * KSTR * 2 + s * 32);
                MMA_F16(S[up * 2],     Qf[s][0], Qf[s][1], Qf[s][2], Qf[s][3],
                        b[0], b[1]);
                MMA_F16(S[up * 2 + 1], Qf[s][0], Qf[s][1], Qf[s][2], Qf[s][3],
                        b[2], b[3]);
            }
        }

        // ---- exp, accumulate l, stage P (fp16) ----
#pragma unroll
        for (int u = 0; u < 8; u++) {
            float p0 = exp_poly(S[u][0]);
            float p1 = exp_poly(S[u][1]);
            float p2 = exp_poly(S[u][2]);
            float p3 = exp_poly(S[u][3]);
            l0 += p0 + p1;
            l1 += p2 + p3;
            *(__half2*)&Ps[(rbase + gid) * PSTR + u * 8 + tig * 2] =
                __floats2half2_rn(p0, p1);
            *(__half2*)&Ps[(rbase + 8 + gid) * PSTR + u * 8 + tig * 2] =
                __floats2half2_rn(p2, p3);
        }
        __syncwarp();

        // ---- O += P . V  (A via ldsm, B via ldsm.trans on raw V) ----
#pragma unroll
        for (int s = 0; s < 4; s++) {            // kv k16 steps
            uint32_t a[4];
            LDSM_X4(a[0], a[1], a[2], a[3], p_lm + s * 32);
#pragma unroll
            for (int db = 0; db < 8; db++) {     // d 16-blocks
                uint32_t b[4];
                LDSM_X4_T(b[0], b[1], b[2], b[3],
                          vB + s * 16 * VSTR * 2 + db * 32);
                MMA_F16(O[db * 2],     a[0], a[1], a[2], a[3], b[0], b[1]);
                MMA_F16(O[db * 2 + 1], a[0], a[1], a[2], a[3], b[2], b[3]);
            }
        }
    }

    // ---- epilogue ----
    l0 += __shfl_xor_sync(0xffffffffu, l0, 1);
    l0 += __shfl_xor_sync(0xffffffffu, l0, 2);
    l1 += __shfl_xor_sync(0xffffffffu, l1, 1);
    l1 += __shfl_xor_sync(0xffffffffu, l1, 2);
    const float inv0 = 1.0f / l0;
    const float inv1 = 1.0f / l1;

    const int r0 = m0 + rbase + gid;
    float* o0 = &out[((size_t)(bb * L_SEQ + r0)) * E_DIM + h * HD];
    float* o1 = &out[((size_t)(bb * L_SEQ + r0 + 8)) * E_DIM + h * HD];
#pragma unroll
    for (int ud = 0; ud < 16; ud++) {
        int col = ud * 8 + tig * 2;
        *(float2*)&o0[col] = make_float2(O[ud][0] * inv0, O[ud][1] * inv0);
        *(float2*)&o1[col] = make_float2(O[ud][2] * inv1, O[ud][3] * inv1);
    }
}

// ===========================================================================
extern "C" void kernel_launch(void* const* d_in, const int* in_sizes, int n_in,
                              void* d_out, int out_size)
{
    (void)in_sizes; (void)n_in; (void)out_size;
    const float* x = (const float*)d_in[0];
    const float* W = (const float*)d_in[1];
    const float* b = (const float*)d_in[2];
    float* out = (float*)d_out;

    __half* xh; cudaGetSymbolAddress((void**)&xh, g_xh);
    __half* wh; cudaGetSymbolAddress((void**)&wh, g_wh);

    // 0) fp32 -> fp16 conversion of x and W
    int nx4 = (M_TOTAL * K_DIM) / 4;
    int nw4 = (N_TOTAL * K_DIM) / 4;
    to_half_kernel<<<(nx4 + 255) / 256, 256>>>(x, xh, nx4);
    to_half_kernel<<<(nw4 + 255) / 256, 256>>>(W, wh, nw4);

    // 1) QKV projection (fp16 MMA) with fused bias + L2-norm epilogue
    cudaFuncSetAttribute(qkv_gemm_h,
                         cudaFuncAttributeMaxDynamicSharedMemorySize, G_SMEM_BYTES);
    qkv_gemm_h<<<dim3(N_TOTAL / 128, M_TOTAL / 128), 256, G_SMEM_BYTES>>>(b);

    // 2) Attention (fp16 MMA, V via ldmatrix.trans)
    cudaFuncSetAttribute(attn_h,
                         cudaFuncAttributeMaxDynamicSharedMemorySize, ATT_SMEM_BYTES);
    attn_h<<<dim3(L_SEQ / 128, B_SZ * NH), 256, ATT_SMEM_BYTES>>>(out);
}